// round 7
// baseline (speedup 1.0000x reference)
#include <cuda_runtime.h>

#define K          84
#define CHUNKS     21          // K/4 (16B chunks per row)
#define NPROTO     10
#define THREADS    32          // one warp per CTA
#define SLOT_ROWS  32          // rows per ring slot
#define NSLOTS     3
#define SLOT_FLOATS (SLOT_ROWS * K)          // 2688
#define SLOT_VEC4   (SLOT_FLOATS / 4)        // 672
#define COPIES_PER_THREAD (SLOT_VEC4 / THREADS)  // 21
#define CTAS_PER_SM 6

// dynamic smem per CTA:
//   slots[3][SLOT_FLOATS]  3 * 10752 B = 32256 B
//   wblk[210] ulonglong2   3360 B
//   w2[16] floats          64 B          -> 35680 B, 6 CTAs/SM
#define SMEM_BYTES (NSLOTS * SLOT_FLOATS * 4 + CHUNKS * NPROTO * 16 + 64)

__device__ __forceinline__ void ffma2(unsigned long long &d,
                                      unsigned long long a,
                                      unsigned long long b) {
    asm("fma.rn.f32x2 %0, %1, %2, %0;" : "+l"(d) : "l"(a), "l"(b));
}
__device__ __forceinline__ float f2lo(unsigned long long v) {
    return __int_as_float((unsigned)(v & 0xffffffffULL));
}
__device__ __forceinline__ float f2hi(unsigned long long v) {
    return __int_as_float((unsigned)(v >> 32));
}
__device__ __forceinline__ void cp_async16(unsigned smem_addr, const void* gptr) {
    asm volatile("cp.async.cg.shared.global [%0], [%1], 16;\n"
                 :: "r"(smem_addr), "l"(gptr));
}
__device__ __forceinline__ void cp_commit() {
    asm volatile("cp.async.commit_group;\n" ::: "memory");
}
__device__ __forceinline__ void cp_wait1() {
    asm volatile("cp.async.wait_group 1;\n" ::: "memory");
}
__device__ __forceinline__ void cp_wait0() {
    asm volatile("cp.async.wait_group 0;\n" ::: "memory");
}

__global__ void __launch_bounds__(THREADS, CTAS_PER_SM)
rbf_kernel(const float* __restrict__ x,
           const float* __restrict__ weight,
           float* __restrict__ out,
           int nrows) {
    extern __shared__ __align__(16) float smem[];
    float* s_slot[NSLOTS];
    s_slot[0] = smem;
    s_slot[1] = smem + SLOT_FLOATS;
    s_slot[2] = smem + 2 * SLOT_FLOATS;
    ulonglong2* s_w = (ulonglong2*)(smem + NSLOTS * SLOT_FLOATS); // [210]
    float* s_w2 = (float*)(s_w + CHUNKS * NPROTO);                // [16]

    const int t = threadIdx.x;

    // ---- weight blocks: s_w[c*10+k] = chunk c of proto k ----
    for (int i = t; i < CHUNKS * NPROTO; i += THREADS) {
        int c = i / NPROTO;
        int k = i - c * NPROTO;
        const float4 v = *(const float4*)(weight + k * K + 4 * c);
        ulonglong2 u;
        u.x = ((unsigned long long)__float_as_uint(v.y) << 32) | __float_as_uint(v.x);
        u.y = ((unsigned long long)__float_as_uint(v.w) << 32) | __float_as_uint(v.z);
        s_w[i] = u;
    }
    if (t < NPROTO) {
        float s = 0.f;
        #pragma unroll
        for (int j = 0; j < K; j++) { float w = weight[t * K + j]; s += w * w; }
        s_w2[t] = s;
    }
    __syncwarp();

    const int nstages = (nrows + SLOT_ROWS - 1) / SLOT_ROWS;
    const int step = gridDim.x;
    int count = 0;
    for (long long s = blockIdx.x; s < nstages; s += step) count++;

    unsigned slot_addr[NSLOTS];
    #pragma unroll
    for (int i = 0; i < NSLOTS; i++)
        slot_addr[i] = (unsigned)__cvta_generic_to_shared(s_slot[i]);

    // issue loads for local stage index j into slot j%3; ALWAYS commits a group
    auto issue_stage = [&](int j) {
        long long stage = (long long)blockIdx.x + (long long)j * step;
        if (stage < nstages) {
            const float4* gx = (const float4*)x + stage * SLOT_VEC4;
            unsigned dst = slot_addr[j % NSLOTS] + t * 16;
            const float4* src = gx + t;
            #pragma unroll
            for (int i = 0; i < COPIES_PER_THREAD; i++)
                cp_async16(dst + i * THREADS * 16, src + i * THREADS);
        }
        cp_commit();
    };

    // ---- prologue: fill all 3 slots ----
    issue_stage(0);
    issue_stage(1);
    issue_stage(2);

    // per-thread epilogue store helper
    auto store_row = [&](long long stage, const unsigned long long* acc,
                         unsigned long long x2v) {
        float x2 = f2lo(x2v) + f2hi(x2v);
        long long r = stage * SLOT_ROWS + t;
        if (r < nrows) {
            float2* o = (float2*)(out + r * NPROTO);
            #pragma unroll
            for (int k = 0; k < 5; k++) {
                float w2a = s_w2[2 * k], w2b = s_w2[2 * k + 1];
                o[k] = make_float2(
                    fmaf(-2.f, f2lo(acc[2 * k])     + f2hi(acc[2 * k]),     x2 + w2a),
                    fmaf(-2.f, f2lo(acc[2 * k + 1]) + f2hi(acc[2 * k + 1]), x2 + w2b));
            }
        }
    };

    int j = 0;
    for (; j + 1 < count; j += 2) {
        // before this pass: groups 0..j+2 committed; leave <=1 pending
        cp_wait1();
        __syncwarp();

        const long long stA = (long long)blockIdx.x + (long long)j * step;
        const long long stB = stA + step;
        const ulonglong2* rowA = (const ulonglong2*)(s_slot[j % NSLOTS] + t * K);
        const ulonglong2* rowB = (const ulonglong2*)(s_slot[(j + 1) % NSLOTS] + t * K);

        unsigned long long accA[NPROTO], accB[NPROTO];
        unsigned long long x2a = 0ULL, x2b = 0ULL;
        #pragma unroll
        for (int k = 0; k < NPROTO; k++) { accA[k] = 0ULL; accB[k] = 0ULL; }

        #pragma unroll
        for (int c = 0; c < CHUNKS; c++) {
            ulonglong2 va = rowA[c];
            ulonglong2 vb = rowB[c];
            ffma2(x2a, va.x, va.x);
            ffma2(x2a, va.y, va.y);
            ffma2(x2b, vb.x, vb.x);
            ffma2(x2b, vb.y, vb.y);
            #pragma unroll
            for (int k = 0; k < NPROTO; k++) {
                ulonglong2 wv = s_w[c * NPROTO + k];
                ffma2(accA[k], va.x, wv.x);
                ffma2(accA[k], va.y, wv.y);
                ffma2(accB[k], vb.x, wv.x);
                ffma2(accB[k], vb.y, wv.y);
            }
        }

        store_row(stA, accA, x2a);
        store_row(stB, accB, x2b);

        __syncwarp();            // slots (j%3),(j+1)%3 fully consumed
        issue_stage(j + 3);      // refills slot j%3
        issue_stage(j + 4);      // refills slot (j+1)%3
    }

    // ---- odd tail: single stage ----
    if (j < count) {
        cp_wait0();
        __syncwarp();

        const long long stA = (long long)blockIdx.x + (long long)j * step;
        const ulonglong2* rowA = (const ulonglong2*)(s_slot[j % NSLOTS] + t * K);

        unsigned long long accA[NPROTO];
        unsigned long long x2a = 0ULL;
        #pragma unroll
        for (int k = 0; k < NPROTO; k++) accA[k] = 0ULL;

        #pragma unroll
        for (int c = 0; c < CHUNKS; c++) {
            ulonglong2 va = rowA[c];
            ffma2(x2a, va.x, va.x);
            ffma2(x2a, va.y, va.y);
            #pragma unroll
            for (int k = 0; k < NPROTO; k++) {
                ulonglong2 wv = s_w[c * NPROTO + k];
                ffma2(accA[k], va.x, wv.x);
                ffma2(accA[k], va.y, wv.y);
            }
        }
        store_row(stA, accA, x2a);
    }
}

extern "C" void kernel_launch(void* const* d_in, const int* in_sizes, int n_in,
                              void* d_out, int out_size) {
    const float* x = (const float*)d_in[0];
    const float* w = (const float*)d_in[1];
    float* out = (float*)d_out;

    const int nrows = in_sizes[0] / K;   // 524288

    static int nsm = 0;
    if (nsm == 0) {
        cudaFuncSetAttribute(rbf_kernel,
                             cudaFuncAttributeMaxDynamicSharedMemorySize,
                             SMEM_BYTES);
        cudaDeviceGetAttribute(&nsm, cudaDevAttrMultiProcessorCount, 0);
        if (nsm <= 0) nsm = 148;
    }

    // 6 single-warp CTAs per SM; each pass computes 2 stages sharing weight LDS
    rbf_kernel<<<CTAS_PER_SM * nsm, THREADS, SMEM_BYTES>>>(x, w, out, nrows);
}